// round 10
// baseline (speedup 1.0000x reference)
#include <cuda_runtime.h>
#include <cuda_bf16.h>

// out[b,c,t] = W[c, idx[b,t]] + bias[c]
//   idx: (256,1,2048) i32, W: (128,32000) f32, b: (128,) f32
//   out: (256,128,2048) f32 = 256 MB  -> store-bound.
//
// K1: W -> WT (V x 128), channel-permuted (chunk k = channels {k,k+32,k+64,k+96}),
//     bias folded. 16.4 MB, L2-resident (output stores use __stcs).
// K2: PERSISTENT: 888 CTAs (1 wave @ 6 CTAs/SM), each owns a contiguous
//     balanced slice of the 16384 32-token tiles. Continuous distance-1
//     software pipeline: prefetch WT rows of tile i+1 (regs) and idx of
//     tile i+2 (smem) while writing tile i. All smem phases conflict-free.

#define BB   256
#define TT   2048
#define VV   32000
#define CC   128
#define TOK  32
#define NTILES ((BB * TT) / TOK)   // 16384
#define GRID_P 888                 // 148 SMs * 6 CTAs
#define TSTR 33                    // odd -> conflict-free

__device__ float g_WT[(size_t)VV * CC];

// ---------------- K1: transpose + channel-permute + bias fold ----------------
__global__ void __launch_bounds__(256, 6)
wt_build_kernel(const float* __restrict__ W, const float* __restrict__ bias) {
    __shared__ float sm[CC][33];
    const int v0 = blockIdx.x * 32;
    const int tid = threadIdx.x;
    const int vl = tid & 31;
    const int cw = tid >> 5;

    #pragma unroll
    for (int it = 0; it < 16; ++it) {
        int c = it * 8 + cw;
        sm[c][vl] = W[(size_t)c * VV + v0 + vl];
    }
    __syncthreads();

    float4* WT4 = reinterpret_cast<float4*>(g_WT);
    #pragma unroll
    for (int it = 0; it < 4; ++it) {
        int li   = it * 256 + tid;
        int vloc = li >> 5;
        int k    = li & 31;
        float4 f;
        f.x = sm[k     ][vloc] + __ldg(&bias[k     ]);
        f.y = sm[k + 32][vloc] + __ldg(&bias[k + 32]);
        f.z = sm[k + 64][vloc] + __ldg(&bias[k + 64]);
        f.w = sm[k + 96][vloc] + __ldg(&bias[k + 96]);
        WT4[(size_t)(v0 + vloc) * 32 + k] = f;
    }
}

// ---------------- K2: persistent pipelined gather ----------------
__global__ void __launch_bounds__(256, 6)
gather_kernel(const int* __restrict__ idx, float* __restrict__ out) {
    __shared__ float tile[2][CC * TSTR];   // 2 x 16.9 KB
    __shared__ int   s_idx[2][TOK];

    const int tid = threadIdx.x;

    // Balanced contiguous tile range for this CTA.
    const int tb = (int)(((long long)blockIdx.x * NTILES) / gridDim.x);
    const int te = (int)(((long long)(blockIdx.x + 1) * NTILES) / gridDim.x);
    const int count = te - tb;             // 18 or 19 for grid=888

    const float4* __restrict__ WT4 = reinterpret_cast<const float4*>(g_WT);
    const int jg = tid >> 5;               // gather: token sub-index (warp-uniform)
    const int k  = tid & 31;               // gather: float4 chunk = lane
    const int c  = tid >> 3;               // write: channel base
    const int t4 = tid & 7;                // write: float4 group along t

    // idx is flat (B*T); tile tau covers flat tokens [tau*32, tau*32+32).
    if (tid < TOK) s_idx[0][tid] = __ldg(&idx[(size_t)tb * TOK + tid]);
    __syncthreads();

    // Prologue: gather tile 0 into buffer 0.
    {
        float* tbuf = tile[0];
        #pragma unroll
        for (int it = 0; it < 4; ++it) {
            int j = it * 8 + jg;
            float4 f = WT4[(size_t)s_idx[0][j] * 32 + k];
            // banks: (k + j) % 32 across lanes -> conflict-free
            tbuf[(k     ) * TSTR + j] = f.x;
            tbuf[(k + 32) * TSTR + j] = f.y;
            tbuf[(k + 64) * TSTR + j] = f.z;
            tbuf[(k + 96) * TSTR + j] = f.w;
        }
    }
    if (count > 1 && tid < TOK)
        s_idx[1][tid] = __ldg(&idx[(size_t)(tb + 1) * TOK + tid]);
    __syncthreads();

    for (int i = 0; i < count; ++i) {
        // (a) Prefetch tile i+1 WT rows (L2 hits) - overlaps write phase.
        float4 pre[4];
        if (i + 1 < count) {
            const int* si = s_idx[(i + 1) & 1];
            #pragma unroll
            for (int it = 0; it < 4; ++it)
                pre[it] = WT4[(size_t)si[it * 8 + jg] * 32 + k];
        }

        // (b) Prefetch idx of tile i+2 into a register (DRAM/L2).
        int iv = 0;
        const bool have2 = (i + 2 < count) && (tid < TOK);
        if (have2) iv = __ldg(&idx[(size_t)(tb + i + 2) * TOK + tid]);

        // (c) Write tile i: coalesced float4 along t, streaming stores.
        {
            const int tau = tb + i;
            const int b   = tau >> 6;              // 64 tiles per batch row
            const int t0  = (tau & 63) * TOK;
            const float* tbuf = tile[i & 1];
            float* outb = out + (size_t)b * CC * TT + t0;
            #pragma unroll
            for (int it = 0; it < 4; ++it) {
                int cc = it * 32 + c;
                // banks: (cc + 4*t4 + m) % 32 -> all distinct: conflict-free
                float4 o;
                o.x = tbuf[cc * TSTR + 4 * t4 + 0];
                o.y = tbuf[cc * TSTR + 4 * t4 + 1];
                o.z = tbuf[cc * TSTR + 4 * t4 + 2];
                o.w = tbuf[cc * TSTR + 4 * t4 + 3];
                __stcs(reinterpret_cast<float4*>(outb + (size_t)cc * TT + 4 * t4), o);
            }
        }

        // (d) Scatter prefetched tile i+1 into other buffer.
        //     Safe: last reads of buf (i+1)&1 ended before barrier of iter i-1.
        if (i + 1 < count) {
            float* nb = tile[(i + 1) & 1];
            #pragma unroll
            for (int it = 0; it < 4; ++it) {
                int j = it * 8 + jg;
                nb[(k     ) * TSTR + j] = pre[it].x;
                nb[(k + 32) * TSTR + j] = pre[it].y;
                nb[(k + 64) * TSTR + j] = pre[it].z;
                nb[(k + 96) * TSTR + j] = pre[it].w;
            }
        }

        // (e) Publish idx of tile i+2 into slot i&1 ( == (i+2)&1 ).
        //     Safe: last read of slot i&1 was prefetch (a) of iter i-1, pre-barrier.
        if (have2) s_idx[i & 1][tid] = iv;

        __syncthreads();
    }
}

extern "C" void kernel_launch(void* const* d_in, const int* in_sizes, int n_in,
                              void* d_out, int out_size) {
    const int*   idx  = (const int*)  d_in[0];
    const float* W    = (const float*)d_in[1];
    const float* bias = (const float*)d_in[2];
    float*       out  = (float*)      d_out;

    wt_build_kernel<<<VV / 32, 256>>>(W, bias);
    gather_kernel<<<GRID_P, 256>>>(idx, out);
}

// round 13
// speedup vs baseline: 1.1092x; 1.1092x over previous
#include <cuda_runtime.h>
#include <cuda_bf16.h>
#include <cstdint>
#include <cstddef>

// out[b,c,t] = W[c, idx[b,t]] + bias[c]
//   idx: (256,1,2048) i32, W: (128,32000) f32, b: (128,) f32
//   out: (256,128,2048) f32 = 256 MB  -> store-bound.
//
// K1: W -> WT (V x 128), chunk k of row v = channels {k,k+32,k+64,k+96},
//     bias folded. 16.4 MB, L2-resident (output uses __stcs streaming).
// K2: 2048 short CTAs (8 tiles of 32 tokens each). 3-stage cp.async pipeline:
//     LDGSTS.16 gathers WT rows into XOR-swizzled token-major smem tiles
//     (no STS, no register staging); consume = 4x LDS.128 (conflict-free)
//     + in-register 4x4 transpose + 4x coalesced STG.128 streamed along t.
//     One __syncthreads per tile.

#define BB   256
#define TT   2048
#define VV   32000
#define CC   128
#define TOK  32
#define NT   8                       // tiles per CTA
#define NSTAGE 3
#define STAGE_FLOATS (TOK * CC)      // 4096 floats = 16 KB
#define SMEM_BYTES (NSTAGE * STAGE_FLOATS * 4 + NT * TOK * 4)   // 50176

__device__ float g_WT[(size_t)VV * CC];

// ---------------- K1: transpose + channel-permute + bias fold ----------------
__global__ void __launch_bounds__(256, 6)
wt_build_kernel(const float* __restrict__ W, const float* __restrict__ bias) {
    __shared__ float sm[CC][33];
    const int v0 = blockIdx.x * 32;
    const int tid = threadIdx.x;
    const int vl = tid & 31;
    const int cw = tid >> 5;

    #pragma unroll
    for (int it = 0; it < 16; ++it) {
        int c = it * 8 + cw;
        sm[c][vl] = W[(size_t)c * VV + v0 + vl];
    }
    __syncthreads();

    float4* WT4 = reinterpret_cast<float4*>(g_WT);
    #pragma unroll
    for (int it = 0; it < 4; ++it) {
        int li   = it * 256 + tid;
        int vloc = li >> 5;
        int k    = li & 31;
        float4 f;
        f.x = sm[k     ][vloc] + __ldg(&bias[k     ]);
        f.y = sm[k + 32][vloc] + __ldg(&bias[k + 32]);
        f.z = sm[k + 64][vloc] + __ldg(&bias[k + 64]);
        f.w = sm[k + 96][vloc] + __ldg(&bias[k + 96]);
        WT4[(size_t)(v0 + vloc) * 32 + k] = f;
    }
}

// Issue gather of tile i into stage s: warp w loads rows it*8+w, lane l
// copies 16B chunk l to physical chunk l ^ (row>>2) (XOR swizzle).
__device__ __forceinline__ void issue_tile(unsigned int sbase, const int* s_idx,
                                           const char* WTb, int i, int s,
                                           int w, int l) {
    unsigned int stg = sbase + (unsigned int)s * (STAGE_FLOATS * 4);
    #pragma unroll
    for (int it = 0; it < 4; ++it) {
        int j = it * 8 + w;
        const char* src = WTb + (size_t)s_idx[i * TOK + j] * 512 + l * 16;
        unsigned int dst = stg + (unsigned int)(j * 512 + ((l ^ (j >> 2)) << 4));
        asm volatile("cp.async.cg.shared.global [%0], [%1], 16;\n"
                     :: "r"(dst), "l"(src));
    }
    asm volatile("cp.async.commit_group;\n");
}

// ---------------- K2: cp.async pipelined gather + register transpose --------
__global__ void __launch_bounds__(256, 4)
gather_kernel(const int* __restrict__ idx, float* __restrict__ out) {
    extern __shared__ float sm[];                    // 3 stages of 4096 floats
    int* s_idx = (int*)(sm + NSTAGE * STAGE_FLOATS); // 256 token ids

    const int tid = threadIdx.x;
    const int w   = tid >> 5;
    const int l   = tid & 31;
    const int tau0 = blockIdx.x * NT;

    s_idx[tid] = idx[(size_t)tau0 * TOK + tid];
    __syncthreads();

    const char* WTb = (const char*)g_WT;
    const unsigned int sbase = (unsigned int)__cvta_generic_to_shared(sm);

    issue_tile(sbase, s_idx, WTb, 0, 0, w, l);
    issue_tile(sbase, s_idx, WTb, 1, 1, w, l);

    const int tg = l & 7;          // token group: tokens 4*tg .. 4*tg+3
    const int cq = l >> 3;
    const int q  = 4 * w + cq;     // logical chunk -> channels {q,q+32,q+64,q+96}
    const int pc = q ^ tg;         // physical chunk (row>>2 == tg for all 4 rows)

    #pragma unroll
    for (int i = 0; i < NT; ++i) {
        if (i < NT - 2) asm volatile("cp.async.wait_group 1;\n");
        else            asm volatile("cp.async.wait_group 0;\n");
        __syncthreads();

        const float* sb = sm + (i % NSTAGE) * STAGE_FLOATS;
        // 4 LDS.128, conflict-free: octet banks (((4w+cq)^tg)&7) all distinct
        // across the 8 tg-phases within each cq group.
        float4 v0 = *(const float4*)(sb + (4 * tg + 0) * CC + pc * 4);
        float4 v1 = *(const float4*)(sb + (4 * tg + 1) * CC + pc * 4);
        float4 v2 = *(const float4*)(sb + (4 * tg + 2) * CC + pc * 4);
        float4 v3 = *(const float4*)(sb + (4 * tg + 3) * CC + pc * 4);

        const int tau = tau0 + i;
        float* ob = out + (size_t)(tau >> 6) * CC * TT + (tau & 63) * TOK + 4 * tg;
        // In-register 4x4 transpose; 4 coalesced STG.128 (full 128B lines/warp).
        float4 o;
        o = make_float4(v0.x, v1.x, v2.x, v3.x);
        __stcs((float4*)(ob + (size_t)(q     ) * TT), o);
        o = make_float4(v0.y, v1.y, v2.y, v3.y);
        __stcs((float4*)(ob + (size_t)(q + 32) * TT), o);
        o = make_float4(v0.z, v1.z, v2.z, v3.z);
        __stcs((float4*)(ob + (size_t)(q + 64) * TT), o);
        o = make_float4(v0.w, v1.w, v2.w, v3.w);
        __stcs((float4*)(ob + (size_t)(q + 96) * TT), o);

        // Bottom-issue tile i+2 into stage (i+2)%3 == (i-1)%3: its last readers
        // (iter i-1) all passed this iteration's barrier -> race-free.
        if (i + 2 < NT)
            issue_tile(sbase, s_idx, WTb, i + 2, (i + 2) % NSTAGE, w, l);
    }
}

extern "C" void kernel_launch(void* const* d_in, const int* in_sizes, int n_in,
                              void* d_out, int out_size) {
    const int*   idx  = (const int*)  d_in[0];
    const float* W    = (const float*)d_in[1];
    const float* bias = (const float*)d_in[2];
    float*       out  = (float*)      d_out;

    cudaFuncSetAttribute(gather_kernel,
                         cudaFuncAttributeMaxDynamicSharedMemorySize, SMEM_BYTES);

    wt_build_kernel<<<VV / 32, 256>>>(W, bias);
    gather_kernel<<<(BB * TT) / (TOK * NT), 256, SMEM_BYTES>>>(idx, out);
}